// round 12
// baseline (speedup 1.0000x reference)
#include <cuda_runtime.h>
#include <cuda_fp16.h>

#define NN 50000
#define NE 800000
#define NG 256
#define F  64

// ---------------- scratch ----------------
__device__ __align__(16) __half g_hh[NN * F];   // h * dinv[src], fp16 (gather payload)
__device__ __align__(16) float g_agg[NN * F];   // self-loop init, then full agg (fp32)
__device__ __align__(16) float g_sums[NG * F];
__device__ float g_cnt[NG];
__device__ float g_dinv[NN];
__device__ float g_invdeg[NN];
__device__ int   g_deg[NN];
__device__ int   g_rowstart[NN];
__device__ int   g_cursor[NN];
__device__ int   g_counter;
__device__ int   g_ssorted[NE];

__device__ __forceinline__ void red_add_v4(float* p, float4 v) {
    asm volatile("red.global.add.v4.f32 [%0], {%1, %2, %3, %4};"
                 :: "l"(p), "f"(v.x), "f"(v.y), "f"(v.z), "f"(v.w) : "memory");
}

// ---------------- prep kernels ----------------
__global__ void zero_kernel() {
    int i = blockIdx.x * blockDim.x + threadIdx.x;
    if (i < NG * F) g_sums[i] = 0.0f;
    if (i < NG) g_cnt[i] = 0.0f;
    if (i == 0) g_counter = 0;
}

// 4 edges/thread (int4): 4 independent atomic chains -> MLP=4
__global__ void deg_kernel(const int4* __restrict__ dst4) {
    int i = blockIdx.x * blockDim.x + threadIdx.x;
    if (i < NE / 4) {
        int4 d = dst4[i];
        atomicAdd(&g_deg[d.x], 1);
        atomicAdd(&g_deg[d.y], 1);
        atomicAdd(&g_deg[d.z], 1);
        atomicAdd(&g_deg[d.w], 1);
    }
}

// Fused: dinv/invdeg/cnt + block-local scan + block-atomic region placement.
__global__ void scan_fused_kernel(const int* __restrict__ batch) {
    __shared__ int s[2][256];
    __shared__ int blockoff;
    int tid = threadIdx.x;
    int i = blockIdx.x * 256 + tid;
    int v = (i < NN) ? g_deg[i] : 0;
    s[0][tid] = v;
    if (i < NN) {
        float d = (float)(v + 1);
        g_dinv[i] = rsqrtf(d);
        g_invdeg[i] = 1.0f / d;
        atomicAdd(&g_cnt[batch[i]], 1.0f);
    }
    __syncthreads();
    int cur = 0;
#pragma unroll
    for (int off = 1; off < 256; off <<= 1) {
        int val = s[cur][tid];
        if (tid >= off) val += s[cur][tid - off];
        s[cur ^ 1][tid] = val;
        cur ^= 1;
        __syncthreads();
    }
    if (tid == 0) blockoff = atomicAdd(&g_counter, s[cur][255]);
    __syncthreads();
    int excl = (tid == 0) ? 0 : s[cur][tid - 1];
    if (i < NN) {
        int rs = excl + blockoff;
        g_rowstart[i] = rs;
        g_cursor[i] = rs;
    }
}

// 4 edges/thread (int4): MLP=4 on the atomic+store chains
__global__ void scatter_kernel(const int4* __restrict__ src4, const int4* __restrict__ dst4) {
    int i = blockIdx.x * blockDim.x + threadIdx.x;
    if (i < NE / 4) {
        int4 s = src4[i];
        int4 d = dst4[i];
        int p0 = atomicAdd(&g_cursor[d.x], 1);
        int p1 = atomicAdd(&g_cursor[d.y], 1);
        int p2 = atomicAdd(&g_cursor[d.z], 1);
        int p3 = atomicAdd(&g_cursor[d.w], 1);
        g_ssorted[p0] = s.x;
        g_ssorted[p1] = s.y;
        g_ssorted[p2] = s.z;
        g_ssorted[p3] = s.w;
    }
}

// ---------------- Tensor-core GEMM + self-loop init ----------------
// in = (FIRST ? x : relu(g_agg + b_prev)); a = in @ W (fp16 in, fp32 accum)
// g_hh = half(a * dinv); g_agg = a * invdeg
// Block: 128 threads = 4 warps; each warp owns 16 nodes (M=16), N=64, K=64.
#define XS_STRIDE 66

template <bool FIRST>
__global__ __launch_bounds__(128) void gemm_tc_kernel(const float* __restrict__ x,
                                                      const float* __restrict__ W,
                                                      const float* __restrict__ bprev) {
    __shared__ __half Wt[F * XS_STRIDE];        // Wt[n][k] = W[k][n]
    __shared__ __half Xs[4][16 * XS_STRIDE];

    int tid = threadIdx.x;
    for (int i = tid; i < F * F; i += 128) {
        int k = i >> 6, n = i & 63;
        Wt[n * XS_STRIDE + k] = __float2half(W[i]);
    }

    int warp = tid >> 5, lane = tid & 31;
    int gid = lane >> 2, tig = lane & 3;
    int nodebase = blockIdx.x * 64 + warp * 16;

    const float4* in4 = FIRST ? (const float4*)x : (const float4*)g_agg;
    const float4* b4 = (const float4*)bprev;
    int hl = lane >> 4;
    int qi = lane & 15;
    __half* Xw = Xs[warp];
#pragma unroll
    for (int rr = 0; rr < 8; ++rr) {
        int r = rr * 2 + hl;
        int node = nodebase + r;
        float4 xv = make_float4(0.f, 0.f, 0.f, 0.f);
        if (node < NN) {
            xv = in4[(size_t)node * 16 + qi];
            if (!FIRST) {
                float4 bv = b4[qi];
                xv.x = fmaxf(xv.x + bv.x, 0.f);
                xv.y = fmaxf(xv.y + bv.y, 0.f);
                xv.z = fmaxf(xv.z + bv.z, 0.f);
                xv.w = fmaxf(xv.w + bv.w, 0.f);
            }
        }
        __half2* p = (__half2*)&Xw[r * XS_STRIDE + qi * 4];
        p[0] = __floats2half2_rn(xv.x, xv.y);
        p[1] = __floats2half2_rn(xv.z, xv.w);
    }
    __syncthreads();

    unsigned a[4][4];
#pragma unroll
    for (int kt = 0; kt < 4; ++kt) {
        int kc = kt * 16 + tig * 2;
        a[kt][0] = *(const unsigned*)&Xw[gid * XS_STRIDE + kc];
        a[kt][1] = *(const unsigned*)&Xw[(gid + 8) * XS_STRIDE + kc];
        a[kt][2] = *(const unsigned*)&Xw[gid * XS_STRIDE + kc + 8];
        a[kt][3] = *(const unsigned*)&Xw[(gid + 8) * XS_STRIDE + kc + 8];
    }

    int row0 = nodebase + gid;
    int row1 = nodebase + gid + 8;
    float dv0 = 0.f, id0 = 0.f, dv1 = 0.f, id1 = 0.f;
    if (row0 < NN) { dv0 = g_dinv[row0]; id0 = g_invdeg[row0]; }
    if (row1 < NN) { dv1 = g_dinv[row1]; id1 = g_invdeg[row1]; }

#pragma unroll
    for (int nt = 0; nt < 8; ++nt) {
        float c0 = 0.f, c1 = 0.f, c2 = 0.f, c3 = 0.f;
        const __half* Wn = &Wt[(nt * 8 + gid) * XS_STRIDE];
#pragma unroll
        for (int kt = 0; kt < 4; ++kt) {
            int kc = kt * 16 + tig * 2;
            unsigned b0 = *(const unsigned*)&Wn[kc];
            unsigned b1 = *(const unsigned*)&Wn[kc + 8];
            asm volatile(
                "mma.sync.aligned.m16n8k16.row.col.f32.f16.f16.f32 "
                "{%0,%1,%2,%3}, {%4,%5,%6,%7}, {%8,%9}, {%0,%1,%2,%3};"
                : "+f"(c0), "+f"(c1), "+f"(c2), "+f"(c3)
                : "r"(a[kt][0]), "r"(a[kt][1]), "r"(a[kt][2]), "r"(a[kt][3]),
                  "r"(b0), "r"(b1));
        }
        int col = nt * 8 + tig * 2;
        if (row0 < NN) {
            *(__half2*)&g_hh[(size_t)row0 * F + col] = __floats2half2_rn(c0 * dv0, c1 * dv0);
            *(float2*)&g_agg[(size_t)row0 * F + col] = make_float2(c0 * id0, c1 * id0);
        }
        if (row1 < NN) {
            *(__half2*)&g_hh[(size_t)row1 * F + col] = __floats2half2_rn(c2 * dv1, c3 * dv1);
            *(float2*)&g_agg[(size_t)row1 * F + col] = make_float2(c2 * id1, c3 * id1);
        }
    }
}

// ---------------- CSR aggregation: 8-lane group per dst, fp16 gather, MLP=4 ----
template <bool LAST>
__global__ __launch_bounds__(256) void agg_kernel(const int* __restrict__ batch,
                                                  const float* __restrict__ b3) {
    int t = blockIdx.x * blockDim.x + threadIdx.x;
    int d = t >> 3;
    int l = t & 7;
    if (d >= NN) return;
    int start = g_rowstart[d];
    int n = g_deg[d];
    const uint4* h4 = (const uint4*)g_hh;

    float acc[8];
#pragma unroll
    for (int j = 0; j < 8; ++j) acc[j] = 0.f;

    int i = 0;
    for (; i + 4 <= n; i += 4) {
        int s0 = g_ssorted[start + i];
        int s1 = g_ssorted[start + i + 1];
        int s2 = g_ssorted[start + i + 2];
        int s3 = g_ssorted[start + i + 3];
        uint4 r0 = h4[(size_t)s0 * 8 + l];
        uint4 r1 = h4[(size_t)s1 * 8 + l];
        uint4 r2 = h4[(size_t)s2 * 8 + l];
        uint4 r3 = h4[(size_t)s3 * 8 + l];
        const __half2* p0 = (const __half2*)&r0;
        const __half2* p1 = (const __half2*)&r1;
        const __half2* p2 = (const __half2*)&r2;
        const __half2* p3 = (const __half2*)&r3;
#pragma unroll
        for (int j = 0; j < 4; ++j) {
            float2 f0 = __half22float2(p0[j]);
            float2 f1 = __half22float2(p1[j]);
            float2 f2 = __half22float2(p2[j]);
            float2 f3 = __half22float2(p3[j]);
            acc[j * 2 + 0] += (f0.x + f1.x) + (f2.x + f3.x);
            acc[j * 2 + 1] += (f0.y + f1.y) + (f2.y + f3.y);
        }
    }
    for (; i < n; ++i) {
        int s0 = g_ssorted[start + i];
        uint4 r0 = h4[(size_t)s0 * 8 + l];
        const __half2* p0 = (const __half2*)&r0;
#pragma unroll
        for (int j = 0; j < 4; ++j) {
            float2 f0 = __half22float2(p0[j]);
            acc[j * 2 + 0] += f0.x;
            acc[j * 2 + 1] += f0.y;
        }
    }

    float dd = g_dinv[d];
    float4* ar = (float4*)(g_agg + (size_t)d * F + l * 8);
    float4 s0v = ar[0];
    float4 s1v = ar[1];
    float4 o0 = make_float4(fmaf(acc[0], dd, s0v.x), fmaf(acc[1], dd, s0v.y),
                            fmaf(acc[2], dd, s0v.z), fmaf(acc[3], dd, s0v.w));
    float4 o1 = make_float4(fmaf(acc[4], dd, s1v.x), fmaf(acc[5], dd, s1v.y),
                            fmaf(acc[6], dd, s1v.z), fmaf(acc[7], dd, s1v.w));
    if (!LAST) {
        ar[0] = o0;
        ar[1] = o1;
    } else {
        float4 b0 = ((const float4*)b3)[l * 2 + 0];
        float4 b1 = ((const float4*)b3)[l * 2 + 1];
        o0.x = fmaxf(o0.x + b0.x, 0.f); o0.y = fmaxf(o0.y + b0.y, 0.f);
        o0.z = fmaxf(o0.z + b0.z, 0.f); o0.w = fmaxf(o0.w + b0.w, 0.f);
        o1.x = fmaxf(o1.x + b1.x, 0.f); o1.y = fmaxf(o1.y + b1.y, 0.f);
        o1.z = fmaxf(o1.z + b1.z, 0.f); o1.w = fmaxf(o1.w + b1.w, 0.f);
        int g = batch[d];
        red_add_v4(g_sums + (size_t)g * F + l * 8, o0);
        red_add_v4(g_sums + (size_t)g * F + l * 8 + 4, o1);
    }
}

// out[g] = (sums[g] . Wl) / max(cnt,1) + bl
__global__ void final_kernel(const float* __restrict__ Wl, const float* __restrict__ bl,
                             float* __restrict__ out) {
    int g = threadIdx.x;
    float c = fmaxf(g_cnt[g], 1.0f);
    float acc = 0.f;
#pragma unroll
    for (int f = 0; f < F; ++f) acc = fmaf(g_sums[g * F + f], Wl[f], acc);
    out[g] = acc / c + bl[0];
}

// ---------------- launch ----------------
extern "C" void kernel_launch(void* const* d_in, const int* in_sizes, int n_in,
                              void* d_out, int out_size) {
    const float* x   = (const float*)d_in[0];
    const int* src   = (const int*)d_in[1];
    const int* dst   = (const int*)d_in[2];
    const int* batch = (const int*)d_in[3];
    const float* W1 = (const float*)d_in[4];
    const float* b1 = (const float*)d_in[5];
    const float* W2 = (const float*)d_in[6];
    const float* b2 = (const float*)d_in[7];
    const float* W3 = (const float*)d_in[8];
    const float* b3 = (const float*)d_in[9];
    const float* Wl = (const float*)d_in[10];
    const float* bl = (const float*)d_in[11];
    float* out = (float*)d_out;

    const int NB_NODE = (NN + 255) / 256;        // 196
    const int NB_E4   = (NE / 4 + 255) / 256;    // 782
    const int NB_GEMM = (NN + 63) / 64;          // 782
    const int NB_AGG  = (NN * 8 + 255) / 256;    // 1563
    const int NB_ZERO = (NG * F + 255) / 256;    // 64

    // one-time side stream + events for the capture fork (created on the
    // pre-capture correctness call; resources persist, work is identical
    // on every call)
    static cudaStream_t side = nullptr;
    static cudaEvent_t ev_fork = nullptr, ev_join = nullptr;
    if (!side) {
        cudaStreamCreateWithFlags(&side, cudaStreamNonBlocking);
        cudaEventCreateWithFlags(&ev_fork, cudaEventDisableTiming);
        cudaEventCreateWithFlags(&ev_join, cudaEventDisableTiming);
    }

    void* deg_ptr = nullptr;
    cudaGetSymbolAddress(&deg_ptr, g_deg);
    cudaMemsetAsync(deg_ptr, 0, NN * sizeof(int));

    zero_kernel<<<NB_ZERO, 256>>>();
    deg_kernel<<<NB_E4, 256>>>((const int4*)dst);
    scan_fused_kernel<<<NB_NODE, 256>>>(batch);

    // fork: scatter (feeds agg1) runs concurrently with gemm1 (needs dinv only)
    cudaEventRecord(ev_fork, 0);
    cudaStreamWaitEvent(side, ev_fork, 0);
    scatter_kernel<<<NB_E4, 256, 0, side>>>((const int4*)src, (const int4*)dst);
    cudaEventRecord(ev_join, side);

    gemm_tc_kernel<true><<<NB_GEMM, 128>>>(x, W1, nullptr);

    cudaStreamWaitEvent(0, ev_join, 0);   // join before agg1

    agg_kernel<false><<<NB_AGG, 256>>>(batch, b3);
    gemm_tc_kernel<false><<<NB_GEMM, 128>>>(nullptr, W2, b1);
    agg_kernel<false><<<NB_AGG, 256>>>(batch, b3);
    gemm_tc_kernel<false><<<NB_GEMM, 128>>>(nullptr, W3, b2);
    agg_kernel<true><<<NB_AGG, 256>>>(batch, b3);

    final_kernel<<<1, 256>>>(Wl, bl, out);
}

// round 13
// speedup vs baseline: 1.0754x; 1.0754x over previous
#include <cuda_runtime.h>
#include <cuda_fp16.h>

#define NN 50000
#define NE 800000
#define NG 256
#define F  64

// ---------------- scratch ----------------
__device__ __align__(16) __half g_hh[NN * F];   // h * dinv[src], fp16 (gather payload)
__device__ __align__(16) float g_agg[NN * F];   // self-loop init, then full agg (fp32)
__device__ __align__(16) float g_sums[NG * F];
__device__ float g_cnt[NG];
__device__ float g_dinv[NN];
__device__ float g_invdeg[NN];
__device__ int   g_deg[NN];                     // total degree (agg row length)
__device__ __align__(16) int g_deg4[NN * 4];    // 4-sharded degree histogram
__device__ int   g_rowstart[NN];
__device__ int   g_cursor4[NN * 4];             // 4-sharded scatter cursors
__device__ int   g_counter;
__device__ int   g_ssorted[NE];

__device__ __forceinline__ void red_add_v4(float* p, float4 v) {
    asm volatile("red.global.add.v4.f32 [%0], {%1, %2, %3, %4};"
                 :: "l"(p), "f"(v.x), "f"(v.y), "f"(v.z), "f"(v.w) : "memory");
}

// ---------------- prep kernels ----------------
__global__ void zero_kernel() {
    int i = blockIdx.x * blockDim.x + threadIdx.x;
    if (i < NN * 4) g_deg4[i] = 0;
    if (i < NG * F) g_sums[i] = 0.0f;
    if (i < NG) g_cnt[i] = 0.0f;
    if (i == 0) g_counter = 0;
}

// sharded histogram: 4x fewer contenders per address
__global__ void deg_kernel(const int* __restrict__ dst) {
    int e = blockIdx.x * blockDim.x + threadIdx.x;
    if (e < NE) atomicAdd(&g_deg4[dst[e] * 4 + (e & 3)], 1);
}

// Fused: dinv/invdeg/cnt + block-local scan + block-atomic region placement
// + per-shard cursor init (shard sub-ranges contiguous within each row).
__global__ void scan_fused_kernel(const int* __restrict__ batch) {
    __shared__ int s[2][256];
    __shared__ int blockoff;
    int tid = threadIdx.x;
    int i = blockIdx.x * 256 + tid;
    int4 dsh = make_int4(0, 0, 0, 0);
    int v = 0;
    if (i < NN) {
        dsh = ((const int4*)g_deg4)[i];
        v = dsh.x + dsh.y + dsh.z + dsh.w;
        g_deg[i] = v;
        float d = (float)(v + 1);
        g_dinv[i] = rsqrtf(d);
        g_invdeg[i] = 1.0f / d;
        atomicAdd(&g_cnt[batch[i]], 1.0f);
    }
    s[0][tid] = v;
    __syncthreads();
    int cur = 0;
#pragma unroll
    for (int off = 1; off < 256; off <<= 1) {
        int val = s[cur][tid];
        if (tid >= off) val += s[cur][tid - off];
        s[cur ^ 1][tid] = val;
        cur ^= 1;
        __syncthreads();
    }
    if (tid == 0) blockoff = atomicAdd(&g_counter, s[cur][255]);
    __syncthreads();
    int excl = (tid == 0) ? 0 : s[cur][tid - 1];
    if (i < NN) {
        int rs = excl + blockoff;
        g_rowstart[i] = rs;
        int4 c;
        c.x = rs;
        c.y = rs + dsh.x;
        c.z = rs + dsh.x + dsh.y;
        c.w = rs + dsh.x + dsh.y + dsh.z;
        ((int4*)g_cursor4)[i] = c;
    }
}

// sharded scatter: 4x fewer contenders per cursor address
__global__ void scatter_kernel(const int* __restrict__ src, const int* __restrict__ dst) {
    int e = blockIdx.x * blockDim.x + threadIdx.x;
    if (e < NE) {
        int d = dst[e];
        int pos = atomicAdd(&g_cursor4[d * 4 + (e & 3)], 1);
        g_ssorted[pos] = src[e];
    }
}

// ---------------- Tensor-core GEMM + self-loop init ----------------
// in = (FIRST ? x : relu(g_agg + b_prev)); a = in @ W (fp16 in, fp32 accum)
// g_hh = half(a * dinv); g_agg = a * invdeg
// Block: 128 threads = 4 warps; each warp owns 16 nodes (M=16), N=64, K=64.
#define XS_STRIDE 66

template <bool FIRST>
__global__ __launch_bounds__(128) void gemm_tc_kernel(const float* __restrict__ x,
                                                      const float* __restrict__ W,
                                                      const float* __restrict__ bprev) {
    __shared__ __half Wt[F * XS_STRIDE];        // Wt[n][k] = W[k][n]
    __shared__ __half Xs[4][16 * XS_STRIDE];

    int tid = threadIdx.x;
    for (int i = tid; i < F * F; i += 128) {
        int k = i >> 6, n = i & 63;
        Wt[n * XS_STRIDE + k] = __float2half(W[i]);
    }

    int warp = tid >> 5, lane = tid & 31;
    int gid = lane >> 2, tig = lane & 3;
    int nodebase = blockIdx.x * 64 + warp * 16;

    const float4* in4 = FIRST ? (const float4*)x : (const float4*)g_agg;
    const float4* b4 = (const float4*)bprev;
    int hl = lane >> 4;
    int qi = lane & 15;
    __half* Xw = Xs[warp];
#pragma unroll
    for (int rr = 0; rr < 8; ++rr) {
        int r = rr * 2 + hl;
        int node = nodebase + r;
        float4 xv = make_float4(0.f, 0.f, 0.f, 0.f);
        if (node < NN) {
            xv = in4[(size_t)node * 16 + qi];
            if (!FIRST) {
                float4 bv = b4[qi];
                xv.x = fmaxf(xv.x + bv.x, 0.f);
                xv.y = fmaxf(xv.y + bv.y, 0.f);
                xv.z = fmaxf(xv.z + bv.z, 0.f);
                xv.w = fmaxf(xv.w + bv.w, 0.f);
            }
        }
        __half2* p = (__half2*)&Xw[r * XS_STRIDE + qi * 4];
        p[0] = __floats2half2_rn(xv.x, xv.y);
        p[1] = __floats2half2_rn(xv.z, xv.w);
    }
    __syncthreads();

    unsigned a[4][4];
#pragma unroll
    for (int kt = 0; kt < 4; ++kt) {
        int kc = kt * 16 + tig * 2;
        a[kt][0] = *(const unsigned*)&Xw[gid * XS_STRIDE + kc];
        a[kt][1] = *(const unsigned*)&Xw[(gid + 8) * XS_STRIDE + kc];
        a[kt][2] = *(const unsigned*)&Xw[gid * XS_STRIDE + kc + 8];
        a[kt][3] = *(const unsigned*)&Xw[(gid + 8) * XS_STRIDE + kc + 8];
    }

    int row0 = nodebase + gid;
    int row1 = nodebase + gid + 8;
    float dv0 = 0.f, id0 = 0.f, dv1 = 0.f, id1 = 0.f;
    if (row0 < NN) { dv0 = g_dinv[row0]; id0 = g_invdeg[row0]; }
    if (row1 < NN) { dv1 = g_dinv[row1]; id1 = g_invdeg[row1]; }

#pragma unroll
    for (int nt = 0; nt < 8; ++nt) {
        float c0 = 0.f, c1 = 0.f, c2 = 0.f, c3 = 0.f;
        const __half* Wn = &Wt[(nt * 8 + gid) * XS_STRIDE];
#pragma unroll
        for (int kt = 0; kt < 4; ++kt) {
            int kc = kt * 16 + tig * 2;
            unsigned b0 = *(const unsigned*)&Wn[kc];
            unsigned b1 = *(const unsigned*)&Wn[kc + 8];
            asm volatile(
                "mma.sync.aligned.m16n8k16.row.col.f32.f16.f16.f32 "
                "{%0,%1,%2,%3}, {%4,%5,%6,%7}, {%8,%9}, {%0,%1,%2,%3};"
                : "+f"(c0), "+f"(c1), "+f"(c2), "+f"(c3)
                : "r"(a[kt][0]), "r"(a[kt][1]), "r"(a[kt][2]), "r"(a[kt][3]),
                  "r"(b0), "r"(b1));
        }
        int col = nt * 8 + tig * 2;
        if (row0 < NN) {
            *(__half2*)&g_hh[(size_t)row0 * F + col] = __floats2half2_rn(c0 * dv0, c1 * dv0);
            *(float2*)&g_agg[(size_t)row0 * F + col] = make_float2(c0 * id0, c1 * id0);
        }
        if (row1 < NN) {
            *(__half2*)&g_hh[(size_t)row1 * F + col] = __floats2half2_rn(c2 * dv1, c3 * dv1);
            *(float2*)&g_agg[(size_t)row1 * F + col] = make_float2(c2 * id1, c3 * id1);
        }
    }
}

// ---------------- CSR aggregation: 8-lane group per dst, fp16 gather, MLP=4 ----
template <bool LAST>
__global__ __launch_bounds__(256) void agg_kernel(const int* __restrict__ batch,
                                                  const float* __restrict__ b3) {
    int t = blockIdx.x * blockDim.x + threadIdx.x;
    int d = t >> 3;
    int l = t & 7;
    if (d >= NN) return;
    int start = g_rowstart[d];
    int n = g_deg[d];
    const uint4* h4 = (const uint4*)g_hh;

    float acc[8];
#pragma unroll
    for (int j = 0; j < 8; ++j) acc[j] = 0.f;

    int i = 0;
    for (; i + 4 <= n; i += 4) {
        int s0 = g_ssorted[start + i];
        int s1 = g_ssorted[start + i + 1];
        int s2 = g_ssorted[start + i + 2];
        int s3 = g_ssorted[start + i + 3];
        uint4 r0 = h4[(size_t)s0 * 8 + l];
        uint4 r1 = h4[(size_t)s1 * 8 + l];
        uint4 r2 = h4[(size_t)s2 * 8 + l];
        uint4 r3 = h4[(size_t)s3 * 8 + l];
        const __half2* p0 = (const __half2*)&r0;
        const __half2* p1 = (const __half2*)&r1;
        const __half2* p2 = (const __half2*)&r2;
        const __half2* p3 = (const __half2*)&r3;
#pragma unroll
        for (int j = 0; j < 4; ++j) {
            float2 f0 = __half22float2(p0[j]);
            float2 f1 = __half22float2(p1[j]);
            float2 f2 = __half22float2(p2[j]);
            float2 f3 = __half22float2(p3[j]);
            acc[j * 2 + 0] += (f0.x + f1.x) + (f2.x + f3.x);
            acc[j * 2 + 1] += (f0.y + f1.y) + (f2.y + f3.y);
        }
    }
    for (; i < n; ++i) {
        int s0 = g_ssorted[start + i];
        uint4 r0 = h4[(size_t)s0 * 8 + l];
        const __half2* p0 = (const __half2*)&r0;
#pragma unroll
        for (int j = 0; j < 4; ++j) {
            float2 f0 = __half22float2(p0[j]);
            acc[j * 2 + 0] += f0.x;
            acc[j * 2 + 1] += f0.y;
        }
    }

    float dd = g_dinv[d];
    float4* ar = (float4*)(g_agg + (size_t)d * F + l * 8);
    float4 s0v = ar[0];
    float4 s1v = ar[1];
    float4 o0 = make_float4(fmaf(acc[0], dd, s0v.x), fmaf(acc[1], dd, s0v.y),
                            fmaf(acc[2], dd, s0v.z), fmaf(acc[3], dd, s0v.w));
    float4 o1 = make_float4(fmaf(acc[4], dd, s1v.x), fmaf(acc[5], dd, s1v.y),
                            fmaf(acc[6], dd, s1v.z), fmaf(acc[7], dd, s1v.w));
    if (!LAST) {
        ar[0] = o0;
        ar[1] = o1;
    } else {
        float4 b0 = ((const float4*)b3)[l * 2 + 0];
        float4 b1 = ((const float4*)b3)[l * 2 + 1];
        o0.x = fmaxf(o0.x + b0.x, 0.f); o0.y = fmaxf(o0.y + b0.y, 0.f);
        o0.z = fmaxf(o0.z + b0.z, 0.f); o0.w = fmaxf(o0.w + b0.w, 0.f);
        o1.x = fmaxf(o1.x + b1.x, 0.f); o1.y = fmaxf(o1.y + b1.y, 0.f);
        o1.z = fmaxf(o1.z + b1.z, 0.f); o1.w = fmaxf(o1.w + b1.w, 0.f);
        int g = batch[d];
        red_add_v4(g_sums + (size_t)g * F + l * 8, o0);
        red_add_v4(g_sums + (size_t)g * F + l * 8 + 4, o1);
    }
}

// out[g] = (sums[g] . Wl) / max(cnt,1) + bl
__global__ void final_kernel(const float* __restrict__ Wl, const float* __restrict__ bl,
                             float* __restrict__ out) {
    int g = threadIdx.x;
    float c = fmaxf(g_cnt[g], 1.0f);
    float acc = 0.f;
#pragma unroll
    for (int f = 0; f < F; ++f) acc = fmaf(g_sums[g * F + f], Wl[f], acc);
    out[g] = acc / c + bl[0];
}

// ---------------- launch ----------------
extern "C" void kernel_launch(void* const* d_in, const int* in_sizes, int n_in,
                              void* d_out, int out_size) {
    const float* x   = (const float*)d_in[0];
    const int* src   = (const int*)d_in[1];
    const int* dst   = (const int*)d_in[2];
    const int* batch = (const int*)d_in[3];
    const float* W1 = (const float*)d_in[4];
    const float* b1 = (const float*)d_in[5];
    const float* W2 = (const float*)d_in[6];
    const float* b2 = (const float*)d_in[7];
    const float* W3 = (const float*)d_in[8];
    const float* b3 = (const float*)d_in[9];
    const float* Wl = (const float*)d_in[10];
    const float* bl = (const float*)d_in[11];
    float* out = (float*)d_out;

    const int NB_NODE = (NN + 255) / 256;        // 196
    const int NB_EDGE = (NE + 255) / 256;        // 3125
    const int NB_GEMM = (NN + 63) / 64;          // 782
    const int NB_AGG  = (NN * 8 + 255) / 256;    // 1563
    const int NB_ZERO = (NN * 4 + 255) / 256;    // 782 (covers deg4/sums/cnt)

    zero_kernel<<<NB_ZERO, 256>>>();
    deg_kernel<<<NB_EDGE, 256>>>(dst);
    scan_fused_kernel<<<NB_NODE, 256>>>(batch);
    scatter_kernel<<<NB_EDGE, 256>>>(src, dst);

    // layer 1
    gemm_tc_kernel<true><<<NB_GEMM, 128>>>(x, W1, nullptr);
    agg_kernel<false><<<NB_AGG, 256>>>(batch, b3);
    // layer 2
    gemm_tc_kernel<false><<<NB_GEMM, 128>>>(nullptr, W2, b1);
    agg_kernel<false><<<NB_AGG, 256>>>(batch, b3);
    // layer 3 (+ fused pool)
    gemm_tc_kernel<false><<<NB_GEMM, 128>>>(nullptr, W3, b2);
    agg_kernel<true><<<NB_AGG, 256>>>(batch, b3);

    final_kernel<<<1, 256>>>(Wl, bl, out);
}